// round 1
// baseline (speedup 1.0000x reference)
#include <cuda_runtime.h>
#include <cuda_bf16.h>
#include <math.h>

// Problem constants
#define BB  2
#define SS  4096
#define HH  2048
#define NHH 8
#define DD  128
#define KDD 1024        // NH*D
#define WW  4
#define MM  (BB*SS)     // 8192
#define HALF_D 64

// ---------------------------------------------------------------------------
// Device scratch (no cudaMalloc allowed)
// ---------------------------------------------------------------------------
__device__ float g_qkv[(size_t)MM * 3 * KDD];   // 96 MB  q|k|v per row
__device__ float g_z  [(size_t)MM * KDD];       // 32 MB
__device__ float g_bg [(size_t)MM * NHH];
__device__ float g_ag [(size_t)MM * NHH];
__device__ float g_att[(size_t)MM * KDD];       // 32 MB
__device__ float g_yn [(size_t)MM * KDD];       // 32 MB
__device__ float g_cos[(size_t)SS * HALF_D];
__device__ float g_sin[(size_t)SS * HALF_D];

// ---------------------------------------------------------------------------
// Tiled SGEMM: C[M,N] = A[M,K] * B[K,N], all row-major, fp32.
// BM=BN=128, BK=16, 256 threads, 8x8 per thread. M,N %128==0, K %16==0.
// ---------------------------------------------------------------------------
__global__ __launch_bounds__(256) void sgemm128(
    const float* __restrict__ A, const float* __restrict__ B,
    float* __restrict__ C, int M, int N, int K)
{
    const int BM = 128, BN = 128, BK = 16, TM = 8, TN = 8;
    __shared__ float As[BK][BM + 4];
    __shared__ float Bs[BK][BN];

    const int tid  = threadIdx.x;
    const int row0 = blockIdx.y * BM;
    const int col0 = blockIdx.x * BN;
    const int tx   = tid & 15;     // 16 cols of threads
    const int ty   = tid >> 4;     // 16 rows of threads

    float acc[TM][TN];
    #pragma unroll
    for (int i = 0; i < TM; i++)
        #pragma unroll
        for (int j = 0; j < TN; j++) acc[i][j] = 0.f;

    for (int k0 = 0; k0 < K; k0 += BK) {
        // Load A tile (BMxBK) transposed into As.  512 float4 loads.
        #pragma unroll
        for (int i = 0; i < 2; i++) {
            int idx = tid + i * 256;          // 0..511
            int r   = idx >> 2;               // 0..127
            int c4  = (idx & 3) * 4;          // 0,4,8,12
            float4 v = *reinterpret_cast<const float4*>(
                &A[(size_t)(row0 + r) * K + k0 + c4]);
            As[c4 + 0][r] = v.x; As[c4 + 1][r] = v.y;
            As[c4 + 2][r] = v.z; As[c4 + 3][r] = v.w;
        }
        // Load B tile (BKxBN) directly.
        #pragma unroll
        for (int i = 0; i < 2; i++) {
            int idx = tid + i * 256;
            int r   = idx >> 5;               // 0..15
            int c4  = (idx & 31) * 4;         // 0..124
            *reinterpret_cast<float4*>(&Bs[r][c4]) =
                *reinterpret_cast<const float4*>(
                    &B[(size_t)(k0 + r) * N + col0 + c4]);
        }
        __syncthreads();

        #pragma unroll
        for (int kk = 0; kk < BK; kk++) {
            float ar[TM], br[TN];
            #pragma unroll
            for (int i = 0; i < TM; i++) ar[i] = As[kk][ty * TM + i];
            #pragma unroll
            for (int j = 0; j < TN; j++) br[j] = Bs[kk][tx * TN + j];
            #pragma unroll
            for (int i = 0; i < TM; i++)
                #pragma unroll
                for (int j = 0; j < TN; j++)
                    acc[i][j] += ar[i] * br[j];
        }
        __syncthreads();
    }

    #pragma unroll
    for (int i = 0; i < TM; i++) {
        size_t r = (size_t)(row0 + ty * TM + i);
        #pragma unroll
        for (int j4 = 0; j4 < TN; j4 += 4) {
            float4 v = make_float4(acc[i][j4], acc[i][j4+1],
                                   acc[i][j4+2], acc[i][j4+3]);
            *reinterpret_cast<float4*>(&C[r * N + col0 + tx * TN + j4]) = v;
        }
    }
}

// ---------------------------------------------------------------------------
// bg = x @ W_b, ag = x @ W_a   (N=8 each). One block per row, 8 warps.
// ---------------------------------------------------------------------------
__global__ __launch_bounds__(256) void proj_gates(
    const float* __restrict__ x, const float* __restrict__ Wb,
    const float* __restrict__ Wa)
{
    __shared__ float xs[HH];
    const int row = blockIdx.x;
    for (int i = threadIdx.x; i < HH / 4; i += blockDim.x)
        reinterpret_cast<float4*>(xs)[i] =
            reinterpret_cast<const float4*>(x + (size_t)row * HH)[i];
    __syncthreads();

    const int w = threadIdx.x >> 5, lane = threadIdx.x & 31;
    float sb = 0.f, sa = 0.f;
    for (int k = lane; k < HH; k += 32) {
        float xv = xs[k];
        sb += xv * Wb[(size_t)k * NHH + w];
        sa += xv * Wa[(size_t)k * NHH + w];
    }
    #pragma unroll
    for (int o = 16; o > 0; o >>= 1) {
        sb += __shfl_down_sync(0xffffffffu, sb, o);
        sa += __shfl_down_sync(0xffffffffu, sa, o);
    }
    if (lane == 0) {
        g_bg[(size_t)row * NHH + w] = sb;
        g_ag[(size_t)row * NHH + w] = sa;
    }
}

// ---------------------------------------------------------------------------
// RoPE tables (double precision internally — bounds deviation from the
// reference's own fp32 rounding well below 1e-3).
// ---------------------------------------------------------------------------
__global__ void rope_tables_k()
{
    int idx = blockIdx.x * blockDim.x + threadIdx.x;
    if (idx >= SS * HALF_D) return;
    int pos = idx / HALF_D, i = idx % HALF_D;
    double inv = exp(-((double)(2 * i) / (double)DD) * log(1.0e6));
    double ang = (double)pos * inv;
    double s, c;
    sincos(ang, &s, &c);
    g_cos[idx] = (float)c;
    g_sin[idx] = (float)s;
}

// Apply RoPE in place to q and k halves of g_qkv.
__global__ void rope_apply_k()
{
    int idx = blockIdx.x * blockDim.x + threadIdx.x;   // M*NH*64
    if (idx >= MM * NHH * HALF_D) return;
    int p = idx % HALF_D;
    int t = idx / HALF_D;
    int h = t % NHH;
    int r = t / NHH;
    int pos = r % SS;
    float c = g_cos[pos * HALF_D + p];
    float s = g_sin[pos * HALF_D + p];

    size_t base = (size_t)r * (3 * KDD) + h * DD + 2 * p;
    float q0 = g_qkv[base], q1 = g_qkv[base + 1];
    g_qkv[base]     = q0 * c - q1 * s;
    g_qkv[base + 1] = q0 * s + q1 * c;

    size_t kb = base + KDD;
    float k0 = g_qkv[kb], k1 = g_qkv[kb + 1];
    g_qkv[kb]     = k0 * c - k1 * s;
    g_qkv[kb + 1] = k0 * s + k1 * c;
}

// ---------------------------------------------------------------------------
// Sliding-window gated attention. One block (128 thr) per (b, s, h).
// ---------------------------------------------------------------------------
__global__ __launch_bounds__(128) void attn_k()
{
    const int s0 = blockIdx.x, h = blockIdx.y, b = blockIdx.z;
    const int d  = threadIdx.x;
    const size_t row = (size_t)b * SS + s0;

    const float vcur = g_qkv[row * (3 * KDD) + 2 * KDD + h * DD + d];
    if (s0 == 0) {
        g_att[row * KDD + h * DD + d] = vcur;   // out[:,0] = v[:,0]
        return;
    }

    const float qd  = g_qkv[row * (3 * KDD) + h * DD + d];
    const float agv = g_ag[row * NHH + h];
    const float scale = 0.08838834764831845f;   // 1/sqrt(128)

    __shared__ float red[4];
    float acc = 0.f;

    #pragma unroll
    for (int off = 0; off <= WW; off++) {
        int j = s0 - off;
        if (j < 0) break;                       // uniform across block
        size_t rowj = (size_t)b * SS + j;
        float kd   = g_qkv[rowj * (3 * KDD) + KDD + h * DD + d];
        float part = qd * kd;
        #pragma unroll
        for (int o = 16; o > 0; o >>= 1)
            part += __shfl_down_sync(0xffffffffu, part, o);
        if ((d & 31) == 0) red[d >> 5] = part;
        __syncthreads();
        float sc = (red[0] + red[1] + red[2] + red[3]) * scale;
        __syncthreads();
        float gate = 1.f / (1.f + expf(-agv * g_bg[rowj * NHH + h]));
        float vj   = g_qkv[rowj * (3 * KDD) + 2 * KDD + h * DD + d];
        acc += sc * gate * vj;
    }
    g_att[row * KDD + h * DD + d] = acc;
}

// ---------------------------------------------------------------------------
// y = att*sigmoid(z); rms over KD; yn = y/rms * norm_w * silu(z).
// One block (256 thr) per row; 4 elements per thread.
// ---------------------------------------------------------------------------
__global__ __launch_bounds__(256) void norm_k(const float* __restrict__ nw)
{
    const int row = blockIdx.x, tid = threadIdx.x;
    const size_t base = (size_t)row * KDD;

    float y[4], zz[4];
    float ss = 0.f;
    #pragma unroll
    for (int i = 0; i < 4; i++) {
        int c   = tid + i * 256;
        float zv  = g_z[base + c];
        float sig = 1.f / (1.f + expf(-zv));
        float yv  = g_att[base + c] * sig;
        y[i]  = yv;
        zz[i] = zv * sig;
        ss   += yv * yv;
    }
    __shared__ float red[8];
    #pragma unroll
    for (int o = 16; o > 0; o >>= 1) ss += __shfl_down_sync(0xffffffffu, ss, o);
    if ((tid & 31) == 0) red[tid >> 5] = ss;
    __syncthreads();
    if (tid < 8) {
        float v = red[tid];
        #pragma unroll
        for (int o = 4; o > 0; o >>= 1) v += __shfl_down_sync(0xffu, v, o);
        if (tid == 0) red[0] = v;
    }
    __syncthreads();
    const float rinv = rsqrtf(red[0] / (float)KDD + 1e-6f);

    #pragma unroll
    for (int i = 0; i < 4; i++) {
        int c = tid + i * 256;
        g_yn[base + c] = y[i] * rinv * nw[c] * zz[i];
    }
}

// ---------------------------------------------------------------------------
// Launch
// ---------------------------------------------------------------------------
extern "C" void kernel_launch(void* const* d_in, const int* in_sizes, int n_in,
                              void* d_out, int out_size)
{
    const float* x    = (const float*)d_in[0];
    const float* Wqkv = (const float*)d_in[1];
    const float* Wz   = (const float*)d_in[2];
    const float* Wb   = (const float*)d_in[3];
    const float* Wa   = (const float*)d_in[4];
    const float* nw   = (const float*)d_in[5];
    const float* Wout = (const float*)d_in[6];
    float* out = (float*)d_out;

    float *p_qkv, *p_z, *p_yn;
    cudaGetSymbolAddress((void**)&p_qkv, g_qkv);
    cudaGetSymbolAddress((void**)&p_z,   g_z);
    cudaGetSymbolAddress((void**)&p_yn,  g_yn);

    // 1) Big projections
    {
        dim3 g1(3 * KDD / 128, MM / 128);
        sgemm128<<<g1, 256>>>(x, Wqkv, p_qkv, MM, 3 * KDD, HH);
        dim3 g2(KDD / 128, MM / 128);
        sgemm128<<<g2, 256>>>(x, Wz, p_z, MM, KDD, HH);
    }
    // 2) Gate projections (N=8 each)
    proj_gates<<<MM, 256>>>(x, Wb, Wa);

    // 3) RoPE
    {
        int n = SS * HALF_D;
        rope_tables_k<<<(n + 255) / 256, 256>>>();
        int m = MM * NHH * HALF_D;
        rope_apply_k<<<(m + 255) / 256, 256>>>();
    }

    // 4) Sliding-window gated attention
    {
        dim3 g(SS, NHH, BB);
        attn_k<<<g, 128>>>();
    }

    // 5) Gated RMS norm
    norm_k<<<MM, 256>>>(nw);

    // 6) Output projection
    {
        dim3 g(HH / 128, MM / 128);
        sgemm128<<<g, 256>>>(p_yn, Wout, out, MM, HH, KDD);
    }
}

// round 2
// speedup vs baseline: 2.1447x; 2.1447x over previous
#include <cuda_runtime.h>
#include <cuda_bf16.h>
#include <math.h>

// Problem constants
#define BB  2
#define SS  4096
#define HH  2048
#define NHH 8
#define DD  128
#define KDD 1024        // NH*D
#define WW  4
#define MM  (BB*SS)     // 8192
#define HALF_D 64

// ---------------------------------------------------------------------------
// Device scratch (no cudaMalloc allowed)
// ---------------------------------------------------------------------------
__device__ float g_qkv[(size_t)MM * 3 * KDD];   // 96 MB  q|k|v per row
__device__ float g_z  [(size_t)MM * KDD];       // 32 MB
__device__ float g_bg [(size_t)MM * NHH];
__device__ float g_ag [(size_t)MM * NHH];
__device__ float g_att[(size_t)MM * KDD];       // 32 MB
__device__ float g_yn [(size_t)MM * KDD];       // 32 MB
__device__ float g_cos[(size_t)SS * HALF_D];
__device__ float g_sin[(size_t)SS * HALF_D];

// ---------------------------------------------------------------------------
// tf32 helpers
// ---------------------------------------------------------------------------
__device__ __forceinline__ unsigned f2tf32(float x) {
    unsigned u;
    asm("cvt.rna.tf32.f32 %0, %1;" : "=r"(u) : "f"(x));
    return u;
}

__device__ __forceinline__ void mma_tf32(float c[4], const unsigned a[4],
                                         const unsigned b[2]) {
    asm volatile(
        "mma.sync.aligned.m16n8k8.row.col.f32.tf32.tf32.f32 "
        "{%0,%1,%2,%3}, {%4,%5,%6,%7}, {%8,%9}, {%0,%1,%2,%3};"
        : "+f"(c[0]), "+f"(c[1]), "+f"(c[2]), "+f"(c[3])
        : "r"(a[0]), "r"(a[1]), "r"(a[2]), "r"(a[3]), "r"(b[0]), "r"(b[1]));
}

// ---------------------------------------------------------------------------
// TF32 tensor-core GEMM: C[M,N] = A[M,K] * B[K,N], row-major fp32 in/out.
// BM=BN=128, BK=32, 256 threads (8 warps, 2x4), warp tile 64x32.
// M,N %128==0, K %32==0. Optional fused RoPE on cols < 2*KDD (qkv GEMM:
// each 128-col block tile is exactly one head, C-frag pairs = rope pairs).
// ---------------------------------------------------------------------------
template <bool ROPE>
__global__ __launch_bounds__(256) void gemm_tf32(
    const float* __restrict__ A, const float* __restrict__ B,
    float* __restrict__ C, int M, int N, int K)
{
    __shared__ float As[128][36];   // stride 36 ≡ 4 (mod 32): frag conflict-free
    __shared__ float Bs[32][136];   // stride 136 ≡ 8 (mod 32): frag conflict-free

    const int tid  = threadIdx.x;
    const int wid  = tid >> 5;
    const int lane = tid & 31;
    const int r4   = lane >> 2;     // 0..7
    const int lc   = lane & 3;      // 0..3

    const int row0 = blockIdx.y * 128;
    const int col0 = blockIdx.x * 128;
    const int warp_row = (wid >> 2) * 64;   // 0 or 64
    const int warp_col = (wid & 3) * 32;    // 0,32,64,96

    float c[4][4][4];
    #pragma unroll
    for (int i = 0; i < 4; i++)
        #pragma unroll
        for (int j = 0; j < 4; j++)
            #pragma unroll
            for (int t = 0; t < 4; t++) c[i][j][t] = 0.f;

    // global->reg tile fetch (4 float4 each for A and B per thread)
    float4 pa[4], pb[4];
    auto load_tiles = [&](int k0) {
        #pragma unroll
        for (int i = 0; i < 4; i++) {
            int idx = tid + i * 256;              // 0..1023
            int ar  = idx >> 3, ac4 = (idx & 7) * 4;
            pa[i] = *reinterpret_cast<const float4*>(
                &A[(size_t)(row0 + ar) * K + k0 + ac4]);
            int br  = idx >> 5, bc4 = (idx & 31) * 4;
            pb[i] = *reinterpret_cast<const float4*>(
                &B[(size_t)(k0 + br) * N + col0 + bc4]);
        }
    };
    auto store_tiles = [&]() {
        #pragma unroll
        for (int i = 0; i < 4; i++) {
            int idx = tid + i * 256;
            int ar  = idx >> 3, ac4 = (idx & 7) * 4;
            float4 va = make_float4(
                __uint_as_float(f2tf32(pa[i].x)), __uint_as_float(f2tf32(pa[i].y)),
                __uint_as_float(f2tf32(pa[i].z)), __uint_as_float(f2tf32(pa[i].w)));
            *reinterpret_cast<float4*>(&As[ar][ac4]) = va;
            int br  = idx >> 5, bc4 = (idx & 31) * 4;
            float4 vb = make_float4(
                __uint_as_float(f2tf32(pb[i].x)), __uint_as_float(f2tf32(pb[i].y)),
                __uint_as_float(f2tf32(pb[i].z)), __uint_as_float(f2tf32(pb[i].w)));
            *reinterpret_cast<float4*>(&Bs[br][bc4]) = vb;
        }
    };

    load_tiles(0);
    store_tiles();
    __syncthreads();

    for (int k0 = 0; k0 < K; k0 += 32) {
        const bool more = (k0 + 32) < K;
        if (more) load_tiles(k0 + 32);

        #pragma unroll
        for (int kc = 0; kc < 4; kc++) {
            const int kc8 = kc * 8;
            unsigned a[4][4], b[4][2];
            #pragma unroll
            for (int mt = 0; mt < 4; mt++) {
                int ar = warp_row + mt * 16 + r4;
                a[mt][0] = __float_as_uint(As[ar    ][kc8 + lc    ]);
                a[mt][1] = __float_as_uint(As[ar + 8][kc8 + lc    ]);
                a[mt][2] = __float_as_uint(As[ar    ][kc8 + lc + 4]);
                a[mt][3] = __float_as_uint(As[ar + 8][kc8 + lc + 4]);
            }
            #pragma unroll
            for (int nt = 0; nt < 4; nt++) {
                int bc = warp_col + nt * 8 + r4;
                b[nt][0] = __float_as_uint(Bs[kc8 + lc    ][bc]);
                b[nt][1] = __float_as_uint(Bs[kc8 + lc + 4][bc]);
            }
            #pragma unroll
            for (int mt = 0; mt < 4; mt++)
                #pragma unroll
                for (int nt = 0; nt < 4; nt++)
                    mma_tf32(c[mt][nt], a[mt], b[nt]);
        }
        __syncthreads();
        if (more) {
            store_tiles();
            __syncthreads();
        }
    }

    // Epilogue: optional fused RoPE (pairs are (2*lc, 2*lc+1) = rope pairs)
    #pragma unroll
    for (int mt = 0; mt < 4; mt++) {
        #pragma unroll
        for (int nt = 0; nt < 4; nt++) {
            int rg = row0 + warp_row + mt * 16 + r4;
            int cg = col0 + warp_col + nt * 8 + 2 * lc;
            float v0 = c[mt][nt][0], v1 = c[mt][nt][1];
            float v2 = c[mt][nt][2], v3 = c[mt][nt][3];
            if (ROPE && cg < 2 * KDD) {
                int p = (cg & (DD - 1)) >> 1;
                int pos0 = rg & (SS - 1);
                int pos1 = (rg + 8) & (SS - 1);
                float c0 = g_cos[pos0 * HALF_D + p], s0 = g_sin[pos0 * HALF_D + p];
                float c1 = g_cos[pos1 * HALF_D + p], s1 = g_sin[pos1 * HALF_D + p];
                float o0 = v0 * c0 - v1 * s0, o1 = v0 * s0 + v1 * c0;
                float o2 = v2 * c1 - v3 * s1, o3 = v2 * s1 + v3 * c1;
                v0 = o0; v1 = o1; v2 = o2; v3 = o3;
            }
            *reinterpret_cast<float2*>(&C[(size_t)rg * N + cg]) =
                make_float2(v0, v1);
            *reinterpret_cast<float2*>(&C[(size_t)(rg + 8) * N + cg]) =
                make_float2(v2, v3);
        }
    }
}

// ---------------------------------------------------------------------------
// bg = x @ W_b, ag = x @ W_a   (N=8 each). One block per row, 8 warps.
// ---------------------------------------------------------------------------
__global__ __launch_bounds__(256) void proj_gates(
    const float* __restrict__ x, const float* __restrict__ Wb,
    const float* __restrict__ Wa)
{
    __shared__ float xs[HH];
    const int row = blockIdx.x;
    for (int i = threadIdx.x; i < HH / 4; i += blockDim.x)
        reinterpret_cast<float4*>(xs)[i] =
            reinterpret_cast<const float4*>(x + (size_t)row * HH)[i];
    __syncthreads();

    const int w = threadIdx.x >> 5, lane = threadIdx.x & 31;
    float sb = 0.f, sa = 0.f;
    for (int k = lane; k < HH; k += 32) {
        float xv = xs[k];
        sb += xv * Wb[(size_t)k * NHH + w];
        sa += xv * Wa[(size_t)k * NHH + w];
    }
    #pragma unroll
    for (int o = 16; o > 0; o >>= 1) {
        sb += __shfl_down_sync(0xffffffffu, sb, o);
        sa += __shfl_down_sync(0xffffffffu, sa, o);
    }
    if (lane == 0) {
        g_bg[(size_t)row * NHH + w] = sb;
        g_ag[(size_t)row * NHH + w] = sa;
    }
}

// ---------------------------------------------------------------------------
// RoPE tables (double precision internally; reference's angle is the fp32
// outer product promoted to f64, matching this closely).
// ---------------------------------------------------------------------------
__global__ void rope_tables_k()
{
    int idx = blockIdx.x * blockDim.x + threadIdx.x;
    if (idx >= SS * HALF_D) return;
    int pos = idx / HALF_D, i = idx % HALF_D;
    double inv = exp(-((double)(2 * i) / (double)DD) * log(1.0e6));
    double ang = (double)pos * inv;
    double s, c;
    sincos(ang, &s, &c);
    g_cos[idx] = (float)c;
    g_sin[idx] = (float)s;
}

// ---------------------------------------------------------------------------
// Sliding-window gated attention. One block (128 thr) per (b, s, h).
// ---------------------------------------------------------------------------
__global__ __launch_bounds__(128) void attn_k()
{
    const int s0 = blockIdx.x, h = blockIdx.y, b = blockIdx.z;
    const int d  = threadIdx.x;
    const size_t row = (size_t)b * SS + s0;

    const float vcur = g_qkv[row * (3 * KDD) + 2 * KDD + h * DD + d];
    if (s0 == 0) {
        g_att[row * KDD + h * DD + d] = vcur;   // out[:,0] = v[:,0]
        return;
    }

    const float qd  = g_qkv[row * (3 * KDD) + h * DD + d];
    const float agv = g_ag[row * NHH + h];
    const float scale = 0.08838834764831845f;   // 1/sqrt(128)

    __shared__ float red[4];
    float acc = 0.f;

    #pragma unroll
    for (int off = 0; off <= WW; off++) {
        int j = s0 - off;
        if (j < 0) break;                       // uniform across block
        size_t rowj = (size_t)b * SS + j;
        float kd   = g_qkv[rowj * (3 * KDD) + KDD + h * DD + d];
        float part = qd * kd;
        #pragma unroll
        for (int o = 16; o > 0; o >>= 1)
            part += __shfl_down_sync(0xffffffffu, part, o);
        if ((d & 31) == 0) red[d >> 5] = part;
        __syncthreads();
        float sc = (red[0] + red[1] + red[2] + red[3]) * scale;
        __syncthreads();
        float gate = 1.f / (1.f + expf(-agv * g_bg[rowj * NHH + h]));
        float vj   = g_qkv[rowj * (3 * KDD) + 2 * KDD + h * DD + d];
        acc += sc * gate * vj;
    }
    g_att[row * KDD + h * DD + d] = acc;
}

// ---------------------------------------------------------------------------
// y = att*sigmoid(z); rms over KD; yn = y/rms * norm_w * silu(z).
// ---------------------------------------------------------------------------
__global__ __launch_bounds__(256) void norm_k(const float* __restrict__ nw)
{
    const int row = blockIdx.x, tid = threadIdx.x;
    const size_t base = (size_t)row * KDD;

    float y[4], zz[4];
    float ss = 0.f;
    #pragma unroll
    for (int i = 0; i < 4; i++) {
        int c   = tid + i * 256;
        float zv  = g_z[base + c];
        float sig = 1.f / (1.f + expf(-zv));
        float yv  = g_att[base + c] * sig;
        y[i]  = yv;
        zz[i] = zv * sig;
        ss   += yv * yv;
    }
    __shared__ float red[8];
    #pragma unroll
    for (int o = 16; o > 0; o >>= 1) ss += __shfl_down_sync(0xffffffffu, ss, o);
    if ((tid & 31) == 0) red[tid >> 5] = ss;
    __syncthreads();
    if (tid < 8) {
        float v = red[tid];
        #pragma unroll
        for (int o = 4; o > 0; o >>= 1) v += __shfl_down_sync(0xffu, v, o);
        if (tid == 0) red[0] = v;
    }
    __syncthreads();
    const float rinv = rsqrtf(red[0] / (float)KDD + 1e-6f);

    #pragma unroll
    for (int i = 0; i < 4; i++) {
        int c = tid + i * 256;
        g_yn[base + c] = y[i] * rinv * nw[c] * zz[i];
    }
}

// ---------------------------------------------------------------------------
// Launch
// ---------------------------------------------------------------------------
extern "C" void kernel_launch(void* const* d_in, const int* in_sizes, int n_in,
                              void* d_out, int out_size)
{
    const float* x    = (const float*)d_in[0];
    const float* Wqkv = (const float*)d_in[1];
    const float* Wz   = (const float*)d_in[2];
    const float* Wb   = (const float*)d_in[3];
    const float* Wa   = (const float*)d_in[4];
    const float* nw   = (const float*)d_in[5];
    const float* Wout = (const float*)d_in[6];
    float* out = (float*)d_out;

    float *p_qkv, *p_z, *p_yn;
    cudaGetSymbolAddress((void**)&p_qkv, g_qkv);
    cudaGetSymbolAddress((void**)&p_z,   g_z);
    cudaGetSymbolAddress((void**)&p_yn,  g_yn);

    // 1) RoPE tables (needed by the qkv GEMM epilogue)
    {
        int n = SS * HALF_D;
        rope_tables_k<<<(n + 255) / 256, 256>>>();
    }

    // 2) Big projections on tensor cores (tf32). qkv has RoPE fused.
    {
        dim3 g1(3 * KDD / 128, MM / 128);
        gemm_tf32<true><<<g1, 256>>>(x, Wqkv, p_qkv, MM, 3 * KDD, HH);
        dim3 g2(KDD / 128, MM / 128);
        gemm_tf32<false><<<g2, 256>>>(x, Wz, p_z, MM, KDD, HH);
    }

    // 3) Gate projections (N=8 each)
    proj_gates<<<MM, 256>>>(x, Wb, Wa);

    // 4) Sliding-window gated attention
    {
        dim3 g(SS, NHH, BB);
        attn_k<<<g, 128>>>();
    }

    // 5) Gated RMS norm
    norm_k<<<MM, 256>>>(nw);

    // 6) Output projection (tf32)
    {
        dim3 g(HH / 128, MM / 128);
        gemm_tf32<false><<<g, 256>>>(p_yn, Wout, out, MM, HH, KDD);
    }
}

// round 3
// speedup vs baseline: 2.8720x; 1.3391x over previous
#include <cuda_runtime.h>
#include <cuda_bf16.h>
#include <math.h>

// Problem constants
#define BB  2
#define SS  4096
#define HH  2048
#define NHH 8
#define DD  128
#define KDD 1024        // NH*D
#define WW  4
#define MM  (BB*SS)     // 8192
#define HALF_D 64

// ---------------------------------------------------------------------------
// Device scratch (no cudaMalloc allowed)
// ---------------------------------------------------------------------------
__device__ float g_qkv[(size_t)MM * 3 * KDD];   // 96 MB  q|k|v per row
__device__ float g_z  [(size_t)MM * KDD];       // 32 MB
__device__ float g_bg [(size_t)MM * NHH];
__device__ float g_ag [(size_t)MM * NHH];
__device__ float g_att[(size_t)MM * KDD];       // 32 MB
__device__ float g_yn [(size_t)MM * KDD];       // 32 MB (tf32-rounded)
__device__ float g_cos[(size_t)SS * HALF_D];
__device__ float g_sin[(size_t)SS * HALF_D];
__device__ float g_xr  [(size_t)MM * HH];       // 64 MB tf32-rounded x
__device__ float g_Wqkvr[(size_t)HH * 3 * KDD]; // 24 MB
__device__ float g_Wzr [(size_t)HH * KDD];      // 8 MB
__device__ float g_Woutr[(size_t)KDD * HH];     // 8 MB
__device__ float g_Wt  [16 * HH];               // transposed Wb|Wa

// ---------------------------------------------------------------------------
// helpers
// ---------------------------------------------------------------------------
__device__ __forceinline__ float f2tf32f(float x) {
    unsigned u;
    asm("cvt.rna.tf32.f32 %0, %1;" : "=r"(u) : "f"(x));
    return __uint_as_float(u);
}

__device__ __forceinline__ void mma_tf32(float c[4], const unsigned a[4],
                                         const unsigned b[2]) {
    asm volatile(
        "mma.sync.aligned.m16n8k8.row.col.f32.tf32.tf32.f32 "
        "{%0,%1,%2,%3}, {%4,%5,%6,%7}, {%8,%9}, {%0,%1,%2,%3};"
        : "+f"(c[0]), "+f"(c[1]), "+f"(c[2]), "+f"(c[3])
        : "r"(a[0]), "r"(a[1]), "r"(a[2]), "r"(a[3]), "r"(b[0]), "r"(b[1]));
}

__device__ __forceinline__ void cp_async16(void* smem, const void* gmem) {
    unsigned s = (unsigned)__cvta_generic_to_shared(smem);
    asm volatile("cp.async.cg.shared.global [%0], [%1], 16;\n" ::
                 "r"(s), "l"(gmem));
}
__device__ __forceinline__ void cp_commit() {
    asm volatile("cp.async.commit_group;\n");
}
template <int N>
__device__ __forceinline__ void cp_wait() {
    asm volatile("cp.async.wait_group %0;\n" :: "n"(N));
}

// ---------------------------------------------------------------------------
// tf32 rounding pass: dst[i] = tf32(src[i])  (float4-vectorized)
// ---------------------------------------------------------------------------
__global__ void round_tf32_k(const float* __restrict__ src,
                             float* __restrict__ dst, int n4)
{
    int i = blockIdx.x * blockDim.x + threadIdx.x;
    if (i >= n4) return;
    float4 v = reinterpret_cast<const float4*>(src)[i];
    v.x = f2tf32f(v.x); v.y = f2tf32f(v.y);
    v.z = f2tf32f(v.z); v.w = f2tf32f(v.w);
    reinterpret_cast<float4*>(dst)[i] = v;
}

// ---------------------------------------------------------------------------
// TF32 tensor-core GEMM with cp.async double buffering.
// C[M,N] = A[M,K] * B[K,N], row-major. Inputs must be pre-rounded to tf32.
// BM=BN=128, BK=32, 256 threads (8 warps 2x4), warp tile 64x32.
// Optional fused RoPE on cols < 2*KDD.
// ---------------------------------------------------------------------------
#define AS_STRIDE 36
#define BS_STRIDE 136
#define AS_FLOATS (128 * AS_STRIDE)   // 4608
#define BS_FLOATS (32 * BS_STRIDE)    // 4352
#define STAGE_FLOATS (AS_FLOATS + BS_FLOATS)

template <bool ROPE>
__global__ __launch_bounds__(256, 2) void gemm_tf32(
    const float* __restrict__ A, const float* __restrict__ B,
    float* __restrict__ C, int M, int N, int K)
{
    extern __shared__ float sm[];
    float* As[2] = { sm, sm + STAGE_FLOATS };
    float* Bs[2] = { sm + AS_FLOATS, sm + STAGE_FLOATS + AS_FLOATS };

    const int tid  = threadIdx.x;
    const int wid  = tid >> 5;
    const int lane = tid & 31;
    const int r4   = lane >> 2;
    const int lc   = lane & 3;

    const int row0 = blockIdx.y * 128;
    const int col0 = blockIdx.x * 128;
    const int warp_row = (wid >> 2) * 64;
    const int warp_col = (wid & 3) * 32;

    // per-thread copy coordinates (4 chunks each of A and B)
    int a_r[4], a_c[4], b_r[4], b_c[4];
    #pragma unroll
    for (int i = 0; i < 4; i++) {
        int idx = tid + i * 256;
        a_r[i] = idx >> 3;  a_c[i] = (idx & 7) * 4;
        b_r[i] = idx >> 5;  b_c[i] = (idx & 31) * 4;
    }

    auto issue = [&](int k0, int st) {
        #pragma unroll
        for (int i = 0; i < 4; i++) {
            cp_async16(&As[st][a_r[i] * AS_STRIDE + a_c[i]],
                       &A[(size_t)(row0 + a_r[i]) * K + k0 + a_c[i]]);
            cp_async16(&Bs[st][b_r[i] * BS_STRIDE + b_c[i]],
                       &B[(size_t)(k0 + b_r[i]) * N + col0 + b_c[i]]);
        }
        cp_commit();
    };

    float c[4][4][4];
    #pragma unroll
    for (int i = 0; i < 4; i++)
        #pragma unroll
        for (int j = 0; j < 4; j++)
            #pragma unroll
            for (int t = 0; t < 4; t++) c[i][j][t] = 0.f;

    const int nk = K >> 5;
    issue(0, 0);

    for (int t = 0; t < nk; t++) {
        const int cur = t & 1;
        if (t + 1 < nk) { issue((t + 1) << 5, cur ^ 1); cp_wait<1>(); }
        else            { cp_wait<0>(); }
        __syncthreads();

        const float* Acur = As[cur];
        const float* Bcur = Bs[cur];
        #pragma unroll
        for (int kc = 0; kc < 4; kc++) {
            const int kc8 = kc * 8;
            unsigned a[4][4], b[4][2];
            #pragma unroll
            for (int mt = 0; mt < 4; mt++) {
                int ar = warp_row + mt * 16 + r4;
                a[mt][0] = __float_as_uint(Acur[(ar    ) * AS_STRIDE + kc8 + lc    ]);
                a[mt][1] = __float_as_uint(Acur[(ar + 8) * AS_STRIDE + kc8 + lc    ]);
                a[mt][2] = __float_as_uint(Acur[(ar    ) * AS_STRIDE + kc8 + lc + 4]);
                a[mt][3] = __float_as_uint(Acur[(ar + 8) * AS_STRIDE + kc8 + lc + 4]);
            }
            #pragma unroll
            for (int nt = 0; nt < 4; nt++) {
                int bc = warp_col + nt * 8 + r4;
                b[nt][0] = __float_as_uint(Bcur[(kc8 + lc    ) * BS_STRIDE + bc]);
                b[nt][1] = __float_as_uint(Bcur[(kc8 + lc + 4) * BS_STRIDE + bc]);
            }
            #pragma unroll
            for (int mt = 0; mt < 4; mt++)
                #pragma unroll
                for (int nt = 0; nt < 4; nt++)
                    mma_tf32(c[mt][nt], a[mt], b[nt]);
        }
        __syncthreads();
    }

    #pragma unroll
    for (int mt = 0; mt < 4; mt++) {
        #pragma unroll
        for (int nt = 0; nt < 4; nt++) {
            int rg = row0 + warp_row + mt * 16 + r4;
            int cg = col0 + warp_col + nt * 8 + 2 * lc;
            float v0 = c[mt][nt][0], v1 = c[mt][nt][1];
            float v2 = c[mt][nt][2], v3 = c[mt][nt][3];
            if (ROPE && cg < 2 * KDD) {
                int p = (cg & (DD - 1)) >> 1;
                int pos0 = rg & (SS - 1);
                int pos1 = (rg + 8) & (SS - 1);
                float c0 = g_cos[pos0 * HALF_D + p], s0 = g_sin[pos0 * HALF_D + p];
                float c1 = g_cos[pos1 * HALF_D + p], s1 = g_sin[pos1 * HALF_D + p];
                float o0 = v0 * c0 - v1 * s0, o1 = v0 * s0 + v1 * c0;
                float o2 = v2 * c1 - v3 * s1, o3 = v2 * s1 + v3 * c1;
                v0 = o0; v1 = o1; v2 = o2; v3 = o3;
            }
            *reinterpret_cast<float2*>(&C[(size_t)rg * N + cg]) =
                make_float2(v0, v1);
            *reinterpret_cast<float2*>(&C[(size_t)(rg + 8) * N + cg]) =
                make_float2(v2, v3);
        }
    }
}

// ---------------------------------------------------------------------------
// Transpose Wb|Wa (HHx8 each) into g_Wt[16][HH]:  n<8 -> Wb, n>=8 -> Wa.
// ---------------------------------------------------------------------------
__global__ void transpose_gates_k(const float* __restrict__ Wb,
                                  const float* __restrict__ Wa)
{
    int idx = blockIdx.x * blockDim.x + threadIdx.x;   // 16*HH
    if (idx >= 16 * HH) return;
    int n = idx / HH, k = idx % HH;
    g_Wt[idx] = (n < 8) ? Wb[(size_t)k * NHH + n]
                        : Wa[(size_t)k * NHH + (n - 8)];
}

// ---------------------------------------------------------------------------
// Gate projections: one block (512 thr) per row; warp n computes output n.
// ---------------------------------------------------------------------------
__global__ __launch_bounds__(512) void proj_gates2(const float* __restrict__ x)
{
    __shared__ float xs[HH];
    const int row = blockIdx.x;
    reinterpret_cast<float4*>(xs)[threadIdx.x] =
        reinterpret_cast<const float4*>(x + (size_t)row * HH)[threadIdx.x];
    __syncthreads();

    const int w = threadIdx.x >> 5, lane = threadIdx.x & 31;
    const float* wt = g_Wt + w * HH;
    float s = 0.f;
    #pragma unroll
    for (int it = 0; it < HH / 128; it++) {
        int k = it * 128 + lane * 4;
        float4 xv = *reinterpret_cast<const float4*>(&xs[k]);
        float4 wv = *reinterpret_cast<const float4*>(&wt[k]);
        s += xv.x * wv.x + xv.y * wv.y + xv.z * wv.z + xv.w * wv.w;
    }
    #pragma unroll
    for (int o = 16; o > 0; o >>= 1) s += __shfl_down_sync(0xffffffffu, s, o);
    if (lane == 0) {
        if (w < 8) g_bg[(size_t)row * NHH + w] = s;
        else       g_ag[(size_t)row * NHH + (w - 8)] = s;
    }
}

// ---------------------------------------------------------------------------
// RoPE tables. Angle computed in fp32 (matching the reference's fp32 outer
// product); inv frequency correctly rounded from double.
// ---------------------------------------------------------------------------
__global__ void rope_tables_k()
{
    int idx = blockIdx.x * blockDim.x + threadIdx.x;
    if (idx >= SS * HALF_D) return;
    int pos = idx / HALF_D, i = idx % HALF_D;
    float inv = (float)exp(-((double)(2 * i) / (double)DD) * log(1.0e6));
    float ang = (float)pos * inv;
    float s, c;
    sincosf(ang, &s, &c);
    g_cos[idx] = c;
    g_sin[idx] = s;
}

// ---------------------------------------------------------------------------
// Sliding-window gated attention. One block (128 thr) per (b, s, h).
// ---------------------------------------------------------------------------
__global__ __launch_bounds__(128) void attn_k()
{
    const int s0 = blockIdx.x, h = blockIdx.y, b = blockIdx.z;
    const int d  = threadIdx.x;
    const size_t row = (size_t)b * SS + s0;

    const float vcur = g_qkv[row * (3 * KDD) + 2 * KDD + h * DD + d];
    if (s0 == 0) {
        g_att[row * KDD + h * DD + d] = vcur;   // out[:,0] = v[:,0]
        return;
    }

    const float qd  = g_qkv[row * (3 * KDD) + h * DD + d];
    const float agv = g_ag[row * NHH + h];
    const float scale = 0.08838834764831845f;   // 1/sqrt(128)

    __shared__ float red[4];
    float acc = 0.f;

    #pragma unroll
    for (int off = 0; off <= WW; off++) {
        int j = s0 - off;
        if (j < 0) break;
        size_t rowj = (size_t)b * SS + j;
        float kd   = g_qkv[rowj * (3 * KDD) + KDD + h * DD + d];
        float part = qd * kd;
        #pragma unroll
        for (int o = 16; o > 0; o >>= 1)
            part += __shfl_down_sync(0xffffffffu, part, o);
        if ((d & 31) == 0) red[d >> 5] = part;
        __syncthreads();
        float sc = (red[0] + red[1] + red[2] + red[3]) * scale;
        __syncthreads();
        float gate = 1.f / (1.f + expf(-agv * g_bg[rowj * NHH + h]));
        float vj   = g_qkv[rowj * (3 * KDD) + 2 * KDD + h * DD + d];
        acc += sc * gate * vj;
    }
    g_att[row * KDD + h * DD + d] = acc;
}

// ---------------------------------------------------------------------------
// y = att*sigmoid(z); rms over KD; yn = tf32(y/rms * norm_w * silu(z)).
// ---------------------------------------------------------------------------
__global__ __launch_bounds__(256) void norm_k(const float* __restrict__ nw)
{
    const int row = blockIdx.x, tid = threadIdx.x;
    const size_t base = (size_t)row * KDD;

    float y[4], zz[4];
    float ss = 0.f;
    #pragma unroll
    for (int i = 0; i < 4; i++) {
        int c   = tid + i * 256;
        float zv  = g_z[base + c];
        float sig = 1.f / (1.f + expf(-zv));
        float yv  = g_att[base + c] * sig;
        y[i]  = yv;
        zz[i] = zv * sig;
        ss   += yv * yv;
    }
    __shared__ float red[8];
    #pragma unroll
    for (int o = 16; o > 0; o >>= 1) ss += __shfl_down_sync(0xffffffffu, ss, o);
    if ((tid & 31) == 0) red[tid >> 5] = ss;
    __syncthreads();
    if (tid < 8) {
        float v = red[tid];
        #pragma unroll
        for (int o = 4; o > 0; o >>= 1) v += __shfl_down_sync(0xffu, v, o);
        if (tid == 0) red[0] = v;
    }
    __syncthreads();
    const float rinv = rsqrtf(red[0] / (float)KDD + 1e-6f);

    #pragma unroll
    for (int i = 0; i < 4; i++) {
        int c = tid + i * 256;
        g_yn[base + c] = f2tf32f(y[i] * rinv * nw[c] * zz[i]);
    }
}

// ---------------------------------------------------------------------------
// Launch
// ---------------------------------------------------------------------------
extern "C" void kernel_launch(void* const* d_in, const int* in_sizes, int n_in,
                              void* d_out, int out_size)
{
    const float* x    = (const float*)d_in[0];
    const float* Wqkv = (const float*)d_in[1];
    const float* Wz   = (const float*)d_in[2];
    const float* Wb   = (const float*)d_in[3];
    const float* Wa   = (const float*)d_in[4];
    const float* nw   = (const float*)d_in[5];
    const float* Wout = (const float*)d_in[6];
    float* out = (float*)d_out;

    float *p_qkv, *p_z, *p_yn, *p_xr, *p_Wqkvr, *p_Wzr, *p_Woutr;
    cudaGetSymbolAddress((void**)&p_qkv,   g_qkv);
    cudaGetSymbolAddress((void**)&p_z,     g_z);
    cudaGetSymbolAddress((void**)&p_yn,    g_yn);
    cudaGetSymbolAddress((void**)&p_xr,    g_xr);
    cudaGetSymbolAddress((void**)&p_Wqkvr, g_Wqkvr);
    cudaGetSymbolAddress((void**)&p_Wzr,   g_Wzr);
    cudaGetSymbolAddress((void**)&p_Woutr, g_Woutr);

    const int smem_bytes = 2 * STAGE_FLOATS * sizeof(float);  // 71680
    static bool attr_set = false;
    if (!attr_set) {
        cudaFuncSetAttribute(gemm_tf32<true>,
            cudaFuncAttributeMaxDynamicSharedMemorySize, smem_bytes);
        cudaFuncSetAttribute(gemm_tf32<false>,
            cudaFuncAttributeMaxDynamicSharedMemorySize, smem_bytes);
        attr_set = true;
    }

    // 1) tf32-round GEMM operands
    {
        int n;
        n = MM * HH / 4;          round_tf32_k<<<(n + 255) / 256, 256>>>(x, p_xr, n);
        n = HH * 3 * KDD / 4;     round_tf32_k<<<(n + 255) / 256, 256>>>(Wqkv, p_Wqkvr, n);
        n = HH * KDD / 4;         round_tf32_k<<<(n + 255) / 256, 256>>>(Wz, p_Wzr, n);
        n = KDD * HH / 4;         round_tf32_k<<<(n + 255) / 256, 256>>>(Wout, p_Woutr, n);
    }

    // 2) RoPE tables + gate weight transpose
    {
        int n = SS * HALF_D;
        rope_tables_k<<<(n + 255) / 256, 256>>>();
        int m = 16 * HH;
        transpose_gates_k<<<(m + 255) / 256, 256>>>(Wb, Wa);
    }

    // 3) Big projections on tensor cores (tf32). qkv has RoPE fused.
    {
        dim3 g1(3 * KDD / 128, MM / 128);
        gemm_tf32<true><<<g1, 256, smem_bytes>>>(p_xr, p_Wqkvr, p_qkv, MM, 3 * KDD, HH);
        dim3 g2(KDD / 128, MM / 128);
        gemm_tf32<false><<<g2, 256, smem_bytes>>>(p_xr, p_Wzr, p_z, MM, KDD, HH);
    }

    // 4) Gate projections
    proj_gates2<<<MM, 512>>>(x);

    // 5) Sliding-window gated attention
    {
        dim3 g(SS, NHH, BB);
        attn_k<<<g, 128>>>();
    }

    // 6) Gated RMS norm (emits tf32-rounded yn)
    norm_k<<<MM, 256>>>(nw);

    // 7) Output projection (tf32)
    {
        dim3 g(HH / 128, MM / 128);
        gemm_tf32<false><<<g, 256, smem_bytes>>>(p_yn, p_Woutr, out, MM, HH, KDD);
    }
}

// round 4
// speedup vs baseline: 3.1099x; 1.0828x over previous
#include <cuda_runtime.h>
#include <cuda_bf16.h>
#include <math.h>

// Problem constants
#define BB  2
#define SS  4096
#define HH  2048
#define NHH 8
#define DD  128
#define KDD 1024        // NH*D
#define WW  4
#define MM  (BB*SS)     // 8192
#define HALF_D 64

// ---------------------------------------------------------------------------
// Device scratch
// ---------------------------------------------------------------------------
__device__ float g_qkv[(size_t)MM * 3 * KDD];   // 96 MB  q|k|v per row
__device__ float g_z  [(size_t)MM * KDD];       // 32 MB
__device__ float g_bg [(size_t)MM * NHH];
__device__ float g_ag [(size_t)MM * NHH];
__device__ float g_att[(size_t)MM * KDD];       // 32 MB
__device__ float g_yn [(size_t)MM * KDD];       // 32 MB (tf32-rounded)
__device__ float g_cos[(size_t)SS * HALF_D];
__device__ float g_sin[(size_t)SS * HALF_D];
__device__ float g_xr  [(size_t)MM * HH];       // tf32-rounded x
__device__ float g_Wqkvr[(size_t)HH * 3 * KDD]; // transposed+rounded [3KDD][HH]
__device__ float g_Wzr [(size_t)HH * KDD];      // transposed+rounded [KDD][HH]
__device__ float g_Woutr[(size_t)KDD * HH];     // transposed+rounded [HH][KDD]
__device__ float g_Wt  [16 * HH];               // transposed Wb|Wa

// ---------------------------------------------------------------------------
// helpers
// ---------------------------------------------------------------------------
__device__ __forceinline__ float f2tf32f(float x) {
    unsigned u;
    asm("cvt.rna.tf32.f32 %0, %1;" : "=r"(u) : "f"(x));
    return __uint_as_float(u);
}

__device__ __forceinline__ void mma_tf32(float c[4], const unsigned a[4],
                                         const unsigned b[2]) {
    asm volatile(
        "mma.sync.aligned.m16n8k8.row.col.f32.tf32.tf32.f32 "
        "{%0,%1,%2,%3}, {%4,%5,%6,%7}, {%8,%9}, {%0,%1,%2,%3};"
        : "+f"(c[0]), "+f"(c[1]), "+f"(c[2]), "+f"(c[3])
        : "r"(a[0]), "r"(a[1]), "r"(a[2]), "r"(a[3]), "r"(b[0]), "r"(b[1]));
}

__device__ __forceinline__ void ldsm_x4(unsigned& r0, unsigned& r1,
                                        unsigned& r2, unsigned& r3,
                                        unsigned addr) {
    asm volatile("ldmatrix.sync.aligned.m8n8.x4.shared.b16 {%0,%1,%2,%3}, [%4];"
                 : "=r"(r0), "=r"(r1), "=r"(r2), "=r"(r3) : "r"(addr));
}

__device__ __forceinline__ void cp_async16(void* smem, const void* gmem) {
    unsigned s = (unsigned)__cvta_generic_to_shared(smem);
    asm volatile("cp.async.cg.shared.global [%0], [%1], 16;\n" ::
                 "r"(s), "l"(gmem));
}
__device__ __forceinline__ void cp_commit() {
    asm volatile("cp.async.commit_group;\n");
}
template <int N>
__device__ __forceinline__ void cp_wait() {
    asm volatile("cp.async.wait_group %0;\n" :: "n"(N));
}

// ---------------------------------------------------------------------------
// tf32 rounding pass (float4)
// ---------------------------------------------------------------------------
__global__ void round_tf32_k(const float* __restrict__ src,
                             float* __restrict__ dst, int n4)
{
    int i = blockIdx.x * blockDim.x + threadIdx.x;
    if (i >= n4) return;
    float4 v = reinterpret_cast<const float4*>(src)[i];
    v.x = f2tf32f(v.x); v.y = f2tf32f(v.y);
    v.z = f2tf32f(v.z); v.w = f2tf32f(v.w);
    reinterpret_cast<float4*>(dst)[i] = v;
}

// ---------------------------------------------------------------------------
// Transpose + tf32 round: src[K][N] -> dst[N][K].  Block (32,8), 32x32 tiles.
// ---------------------------------------------------------------------------
__global__ void transpose_round_k(const float* __restrict__ src,
                                  float* __restrict__ dst, int Kdim, int Ndim)
{
    __shared__ float t[32][33];
    int n0 = blockIdx.x * 32, k0 = blockIdx.y * 32;
    int tx = threadIdx.x, ty = threadIdx.y;
    #pragma unroll
    for (int i = 0; i < 4; i++)
        t[ty + i * 8][tx] =
            f2tf32f(src[(size_t)(k0 + ty + i * 8) * Ndim + n0 + tx]);
    __syncthreads();
    #pragma unroll
    for (int i = 0; i < 4; i++)
        dst[(size_t)(n0 + ty + i * 8) * Kdim + k0 + tx] = t[tx][ty + i * 8];
}

// ---------------------------------------------------------------------------
// TF32 GEMM, ldmatrix fragments, cp.async double buffering.
// C[M,N] = A[M,K] * Bt[N,K]^T. A row-major [M][K], Bt row-major [N][K],
// both pre-rounded to tf32. BM=BN=128, BK=32, 256 thr (8 warps 2x4).
// Optional fused RoPE on cols < 2*KDD.
// ---------------------------------------------------------------------------
#define TS_STRIDE 36
#define TILE_FLOATS (128 * TS_STRIDE)          // 4608
#define STAGE_FLOATS (2 * TILE_FLOATS)         // A + B
#define STAGE_BYTES (STAGE_FLOATS * 4)

template <bool ROPE>
__global__ __launch_bounds__(256, 2) void gemm_tf32(
    const float* __restrict__ A, const float* __restrict__ Bt,
    float* __restrict__ C, int M, int N, int K)
{
    extern __shared__ float sm[];
    const unsigned smem_u32 = (unsigned)__cvta_generic_to_shared(sm);

    const int tid  = threadIdx.x;
    const int wid  = tid >> 5;
    const int lane = tid & 31;
    const int r4   = lane >> 2;
    const int lc   = lane & 3;

    const int row0 = blockIdx.y * 128;
    const int col0 = blockIdx.x * 128;
    const int warp_row = (wid >> 2) * 64;
    const int warp_col = (wid & 3) * 32;

    // copy coordinates: 4 chunks each (row = idx>>3, col4 = (idx&7)*4)
    int cp_r[4], cp_c[4];
    #pragma unroll
    for (int i = 0; i < 4; i++) {
        int idx = tid + i * 256;
        cp_r[i] = idx >> 3;  cp_c[i] = (idx & 7) * 4;
    }

    auto issue = [&](int k0, int st) {
        float* As = sm + st * STAGE_FLOATS;
        float* Bs = As + TILE_FLOATS;
        #pragma unroll
        for (int i = 0; i < 4; i++) {
            cp_async16(&As[cp_r[i] * TS_STRIDE + cp_c[i]],
                       &A[(size_t)(row0 + cp_r[i]) * K + k0 + cp_c[i]]);
            cp_async16(&Bs[cp_r[i] * TS_STRIDE + cp_c[i]],
                       &Bt[(size_t)(col0 + cp_r[i]) * K + k0 + cp_c[i]]);
        }
        cp_commit();
    };

    // ldmatrix lane address components
    const int lrow = lane & 15;
    const int lcolb = (lane & 16) ? 16 : 0;    // byte offset (4 floats)
    const unsigned a_lane = smem_u32 +
        (unsigned)((warp_row + lrow) * TS_STRIDE * 4) + lcolb;
    const unsigned b_lane = smem_u32 + TILE_FLOATS * 4 +
        (unsigned)((warp_col + lrow) * TS_STRIDE * 4) + lcolb;

    float c[4][4][4];
    #pragma unroll
    for (int i = 0; i < 4; i++)
        #pragma unroll
        for (int j = 0; j < 4; j++)
            #pragma unroll
            for (int t = 0; t < 4; t++) c[i][j][t] = 0.f;

    const int nk = K >> 5;
    issue(0, 0);

    for (int t = 0; t < nk; t++) {
        const int cur = t & 1;
        if (t + 1 < nk) { issue((t + 1) << 5, cur ^ 1); cp_wait<1>(); }
        else            { cp_wait<0>(); }
        __syncthreads();

        const unsigned a_st = a_lane + cur * STAGE_BYTES;
        const unsigned b_st = b_lane + cur * STAGE_BYTES;
        #pragma unroll
        for (int kc = 0; kc < 4; kc++) {
            const unsigned koff = kc * 32;     // kc*8 floats
            unsigned a[4][4], b[4][2];
            #pragma unroll
            for (int mt = 0; mt < 4; mt++)
                ldsm_x4(a[mt][0], a[mt][1], a[mt][2], a[mt][3],
                        a_st + (unsigned)(mt * 16 * TS_STRIDE * 4) + koff);
            #pragma unroll
            for (int np = 0; np < 2; np++)
                ldsm_x4(b[2*np][0], b[2*np+1][0], b[2*np][1], b[2*np+1][1],
                        b_st + (unsigned)(np * 16 * TS_STRIDE * 4) + koff);
            #pragma unroll
            for (int mt = 0; mt < 4; mt++)
                #pragma unroll
                for (int nt = 0; nt < 4; nt++)
                    mma_tf32(c[mt][nt], a[mt], b[nt]);
        }
        __syncthreads();
    }

    #pragma unroll
    for (int mt = 0; mt < 4; mt++) {
        #pragma unroll
        for (int nt = 0; nt < 4; nt++) {
            int rg = row0 + warp_row + mt * 16 + r4;
            int cg = col0 + warp_col + nt * 8 + 2 * lc;
            float v0 = c[mt][nt][0], v1 = c[mt][nt][1];
            float v2 = c[mt][nt][2], v3 = c[mt][nt][3];
            if (ROPE && cg < 2 * KDD) {
                int p = (cg & (DD - 1)) >> 1;
                int pos0 = rg & (SS - 1);
                int pos1 = (rg + 8) & (SS - 1);
                float c0 = g_cos[pos0 * HALF_D + p], s0 = g_sin[pos0 * HALF_D + p];
                float c1 = g_cos[pos1 * HALF_D + p], s1 = g_sin[pos1 * HALF_D + p];
                float o0 = v0 * c0 - v1 * s0, o1 = v0 * s0 + v1 * c0;
                float o2 = v2 * c1 - v3 * s1, o3 = v2 * s1 + v3 * c1;
                v0 = o0; v1 = o1; v2 = o2; v3 = o3;
            }
            *reinterpret_cast<float2*>(&C[(size_t)rg * N + cg]) =
                make_float2(v0, v1);
            *reinterpret_cast<float2*>(&C[(size_t)(rg + 8) * N + cg]) =
                make_float2(v2, v3);
        }
    }
}

// ---------------------------------------------------------------------------
// Transpose Wb|Wa (HHx8 each) into g_Wt[16][HH]
// ---------------------------------------------------------------------------
__global__ void transpose_gates_k(const float* __restrict__ Wb,
                                  const float* __restrict__ Wa)
{
    int idx = blockIdx.x * blockDim.x + threadIdx.x;
    if (idx >= 16 * HH) return;
    int n = idx / HH, k = idx % HH;
    g_Wt[idx] = (n < 8) ? Wb[(size_t)k * NHH + n]
                        : Wa[(size_t)k * NHH + (n - 8)];
}

// ---------------------------------------------------------------------------
// Gate projections: one block (512 thr) per row; warp n computes output n.
// ---------------------------------------------------------------------------
__global__ __launch_bounds__(512) void proj_gates2(const float* __restrict__ x)
{
    __shared__ float xs[HH];
    const int row = blockIdx.x;
    reinterpret_cast<float4*>(xs)[threadIdx.x] =
        reinterpret_cast<const float4*>(x + (size_t)row * HH)[threadIdx.x];
    __syncthreads();

    const int w = threadIdx.x >> 5, lane = threadIdx.x & 31;
    const float* wt = g_Wt + w * HH;
    float s = 0.f;
    #pragma unroll
    for (int it = 0; it < HH / 128; it++) {
        int k = it * 128 + lane * 4;
        float4 xv = *reinterpret_cast<const float4*>(&xs[k]);
        float4 wv = *reinterpret_cast<const float4*>(&wt[k]);
        s += xv.x * wv.x + xv.y * wv.y + xv.z * wv.z + xv.w * wv.w;
    }
    #pragma unroll
    for (int o = 16; o > 0; o >>= 1) s += __shfl_down_sync(0xffffffffu, s, o);
    if (lane == 0) {
        if (w < 8) g_bg[(size_t)row * NHH + w] = s;
        else       g_ag[(size_t)row * NHH + (w - 8)] = s;
    }
}

// ---------------------------------------------------------------------------
// RoPE tables (fp32 angle, double inv-freq)
// ---------------------------------------------------------------------------
__global__ void rope_tables_k()
{
    int idx = blockIdx.x * blockDim.x + threadIdx.x;
    if (idx >= SS * HALF_D) return;
    int pos = idx / HALF_D, i = idx % HALF_D;
    float inv = (float)exp(-((double)(2 * i) / (double)DD) * log(1.0e6));
    float ang = (float)pos * inv;
    float s, c;
    sincosf(ang, &s, &c);
    g_cos[idx] = c;
    g_sin[idx] = s;
}

// ---------------------------------------------------------------------------
// Tiled sliding-window gated attention.
// One block (256 thr = 8 warps) per (b, h, 32-query chunk). k/v/bg rows
// [s0-4, s0+32) staged in smem; each warp handles 4 queries.
// ---------------------------------------------------------------------------
#define ATS 32
__global__ __launch_bounds__(256) void attn2_k()
{
    __shared__ float ks[36 * DD];
    __shared__ float vs[36 * DD];
    __shared__ float bgs[36];
    __shared__ float ags[ATS];

    const int s_base = blockIdx.x * ATS;
    const int h = blockIdx.y, b = blockIdx.z;
    const int tid = threadIdx.x;
    const int wid = tid >> 5, lane = tid & 31;

    // stage k/v rows (li = 0..35 -> global j = s_base-4+li)
    for (int t = tid; t < 36 * 32; t += 256) {
        int li = t >> 5, c4 = (t & 31) * 4;
        int j = s_base - 4 + li;
        float4 kv = make_float4(0.f, 0.f, 0.f, 0.f), vv = kv;
        if (j >= 0) {
            size_t r = (size_t)(b * SS + j) * (3 * KDD) + h * DD + c4;
            kv = *reinterpret_cast<const float4*>(&g_qkv[r + KDD]);
            vv = *reinterpret_cast<const float4*>(&g_qkv[r + 2 * KDD]);
        }
        *reinterpret_cast<float4*>(&ks[li * DD + c4]) = kv;
        *reinterpret_cast<float4*>(&vs[li * DD + c4]) = vv;
    }
    if (tid < 36) {
        int j = s_base - 4 + tid;
        bgs[tid] = (j >= 0) ? g_bg[(size_t)(b * SS + j) * NHH + h] : 0.f;
    }
    if (tid >= 64 && tid < 64 + ATS)
        ags[tid - 64] = g_ag[(size_t)(b * SS + s_base + tid - 64) * NHH + h];
    __syncthreads();

    const float scale = 0.08838834764831845f;   // 1/sqrt(128)

    #pragma unroll
    for (int i = 0; i < 4; i++) {
        const int sl = wid + 8 * i;
        const int s  = s_base + sl;
        const size_t orow = (size_t)(b * SS + s) * KDD + h * DD + lane * 4;

        if (s == 0) {
            *reinterpret_cast<float4*>(&g_att[orow]) =
                *reinterpret_cast<const float4*>(&vs[4 * DD + lane * 4]);
            continue;
        }

        const float4 q4 = *reinterpret_cast<const float4*>(
            &g_qkv[(size_t)(b * SS + s) * (3 * KDD) + h * DD + lane * 4]);
        const float agv = ags[sl];
        float4 acc = make_float4(0.f, 0.f, 0.f, 0.f);

        #pragma unroll
        for (int off = 0; off <= WW; off++) {
            if (s - off < 0) continue;
            const int li = sl + 4 - off;
            const float4 k4 = *reinterpret_cast<const float4*>(
                &ks[li * DD + lane * 4]);
            float part = q4.x * k4.x + q4.y * k4.y + q4.z * k4.z + q4.w * k4.w;
            #pragma unroll
            for (int o = 16; o > 0; o >>= 1)
                part += __shfl_xor_sync(0xffffffffu, part, o);
            const float gate = 1.f / (1.f + expf(-agv * bgs[li]));
            const float wgt = part * scale * gate;
            const float4 v4 = *reinterpret_cast<const float4*>(
                &vs[li * DD + lane * 4]);
            acc.x += wgt * v4.x; acc.y += wgt * v4.y;
            acc.z += wgt * v4.z; acc.w += wgt * v4.w;
        }
        *reinterpret_cast<float4*>(&g_att[orow]) = acc;
    }
}

// ---------------------------------------------------------------------------
// y = att*sigmoid(z); rms over KD; yn = tf32(y/rms * norm_w * silu(z)).
// ---------------------------------------------------------------------------
__global__ __launch_bounds__(256) void norm_k(const float* __restrict__ nw)
{
    const int row = blockIdx.x, tid = threadIdx.x;
    const size_t base = (size_t)row * KDD;

    float y[4], zz[4];
    float ss = 0.f;
    #pragma unroll
    for (int i = 0; i < 4; i++) {
        int c   = tid + i * 256;
        float zv  = g_z[base + c];
        float sig = 1.f / (1.f + expf(-zv));
        float yv  = g_att[base + c] * sig;
        y[i]  = yv;
        zz[i] = zv * sig;
        ss   += yv * yv;
    }
    __shared__ float red[8];
    #pragma unroll
    for (int o = 16; o > 0; o >>= 1) ss += __shfl_down_sync(0xffffffffu, ss, o);
    if ((tid & 31) == 0) red[tid >> 5] = ss;
    __syncthreads();
    if (tid < 8) {
        float v = red[tid];
        #pragma unroll
        for (int o = 4; o > 0; o >>= 1) v += __shfl_down_sync(0xffu, v, o);
        if (tid == 0) red[0] = v;
    }
    __syncthreads();
    const float rinv = rsqrtf(red[0] / (float)KDD + 1e-6f);

    #pragma unroll
    for (int i = 0; i < 4; i++) {
        int c = tid + i * 256;
        g_yn[base + c] = f2tf32f(y[i] * rinv * nw[c] * zz[i]);
    }
}

// ---------------------------------------------------------------------------
// Launch
// ---------------------------------------------------------------------------
extern "C" void kernel_launch(void* const* d_in, const int* in_sizes, int n_in,
                              void* d_out, int out_size)
{
    const float* x    = (const float*)d_in[0];
    const float* Wqkv = (const float*)d_in[1];
    const float* Wz   = (const float*)d_in[2];
    const float* Wb   = (const float*)d_in[3];
    const float* Wa   = (const float*)d_in[4];
    const float* nw   = (const float*)d_in[5];
    const float* Wout = (const float*)d_in[6];
    float* out = (float*)d_out;

    float *p_qkv, *p_z, *p_yn, *p_xr, *p_Wqkvr, *p_Wzr, *p_Woutr;
    cudaGetSymbolAddress((void**)&p_qkv,   g_qkv);
    cudaGetSymbolAddress((void**)&p_z,     g_z);
    cudaGetSymbolAddress((void**)&p_yn,    g_yn);
    cudaGetSymbolAddress((void**)&p_xr,    g_xr);
    cudaGetSymbolAddress((void**)&p_Wqkvr, g_Wqkvr);
    cudaGetSymbolAddress((void**)&p_Wzr,   g_Wzr);
    cudaGetSymbolAddress((void**)&p_Woutr, g_Woutr);

    const int smem_bytes = 2 * STAGE_BYTES;   // 73728
    static bool attr_set = false;
    if (!attr_set) {
        cudaFuncSetAttribute(gemm_tf32<true>,
            cudaFuncAttributeMaxDynamicSharedMemorySize, smem_bytes);
        cudaFuncSetAttribute(gemm_tf32<false>,
            cudaFuncAttributeMaxDynamicSharedMemorySize, smem_bytes);
        attr_set = true;
    }

    // 1) Round x; transpose+round weights; rope tables; gate transpose
    {
        int n = MM * HH / 4;
        round_tf32_k<<<(n + 255) / 256, 256>>>(x, p_xr, n);
        dim3 blk(32, 8);
        transpose_round_k<<<dim3(3 * KDD / 32, HH / 32), blk>>>(Wqkv, p_Wqkvr, HH, 3 * KDD);
        transpose_round_k<<<dim3(KDD / 32, HH / 32),     blk>>>(Wz,   p_Wzr,   HH, KDD);
        transpose_round_k<<<dim3(HH / 32, KDD / 32),     blk>>>(Wout, p_Woutr, KDD, HH);
        int t = SS * HALF_D;
        rope_tables_k<<<(t + 255) / 256, 256>>>();
        int m = 16 * HH;
        transpose_gates_k<<<(m + 255) / 256, 256>>>(Wb, Wa);
    }

    // 2) Big projections (tf32, ldmatrix). qkv has RoPE fused.
    {
        dim3 g1(3 * KDD / 128, MM / 128);
        gemm_tf32<true><<<g1, 256, smem_bytes>>>(p_xr, p_Wqkvr, p_qkv, MM, 3 * KDD, HH);
        dim3 g2(KDD / 128, MM / 128);
        gemm_tf32<false><<<g2, 256, smem_bytes>>>(p_xr, p_Wzr, p_z, MM, KDD, HH);
    }

    // 3) Gate projections
    proj_gates2<<<MM, 512>>>(x);

    // 4) Tiled sliding-window gated attention
    {
        dim3 g(SS / ATS, NHH, BB);
        attn2_k<<<g, 256>>>();
    }

    // 5) Gated RMS norm (emits tf32-rounded yn)
    norm_k<<<MM, 256>>>(nw);

    // 6) Output projection
    {
        dim3 g(HH / 128, MM / 128);
        gemm_tf32<false><<<g, 256, smem_bytes>>>(p_yn, p_Woutr, out, MM, HH, KDD);
    }
}

// round 5
// speedup vs baseline: 3.2084x; 1.0317x over previous
#include <cuda_runtime.h>
#include <cuda_bf16.h>
#include <math.h>

// Problem constants
#define BB  2
#define SS  4096
#define HH  2048
#define NHH 8
#define DD  128
#define KDD 1024        // NH*D
#define WW  4
#define MM  (BB*SS)     // 8192
#define HALF_D 64
#define NCOMB (4 * KDD) // 4096 = 3KDD (qkv) + KDD (z)

// ---------------------------------------------------------------------------
// Device scratch
// ---------------------------------------------------------------------------
__device__ float g_qkv[(size_t)MM * 3 * KDD];   // q|k|v per row
__device__ float g_z  [(size_t)MM * KDD];
__device__ float g_bg [(size_t)MM * NHH];
__device__ float g_ag [(size_t)MM * NHH];
__device__ float g_att[(size_t)MM * KDD];
__device__ float g_yn [(size_t)MM * KDD];       // tf32-rounded
__device__ float g_cos[(size_t)SS * HALF_D];
__device__ float g_sin[(size_t)SS * HALF_D];
__device__ float g_xr  [(size_t)MM * HH];       // tf32-rounded x
__device__ float g_Wcomb[(size_t)NCOMB * HH];   // [Wqkv^T | Wz^T] rounded
__device__ float g_Woutr[(size_t)HH * KDD];     // Wout^T rounded [HH][KDD]
__device__ float g_Wt  [16 * HH];               // transposed Wb|Wa

// ---------------------------------------------------------------------------
// helpers
// ---------------------------------------------------------------------------
__device__ __forceinline__ float f2tf32f(float x) {
    unsigned u;
    asm("cvt.rna.tf32.f32 %0, %1;" : "=r"(u) : "f"(x));
    return __uint_as_float(u);
}

__device__ __forceinline__ void mma_tf32(float c[4], const unsigned a[4],
                                         const unsigned b[2]) {
    asm volatile(
        "mma.sync.aligned.m16n8k8.row.col.f32.tf32.tf32.f32 "
        "{%0,%1,%2,%3}, {%4,%5,%6,%7}, {%8,%9}, {%0,%1,%2,%3};"
        : "+f"(c[0]), "+f"(c[1]), "+f"(c[2]), "+f"(c[3])
        : "r"(a[0]), "r"(a[1]), "r"(a[2]), "r"(a[3]), "r"(b[0]), "r"(b[1]));
}

__device__ __forceinline__ void ldsm_x4(unsigned& r0, unsigned& r1,
                                        unsigned& r2, unsigned& r3,
                                        unsigned addr) {
    asm volatile("ldmatrix.sync.aligned.m8n8.x4.shared.b16 {%0,%1,%2,%3}, [%4];"
                 : "=r"(r0), "=r"(r1), "=r"(r2), "=r"(r3) : "r"(addr));
}

__device__ __forceinline__ void cp_async16(void* smem, const void* gmem) {
    unsigned s = (unsigned)__cvta_generic_to_shared(smem);
    asm volatile("cp.async.cg.shared.global [%0], [%1], 16;\n" ::
                 "r"(s), "l"(gmem));
}
__device__ __forceinline__ void cp_commit() {
    asm volatile("cp.async.commit_group;\n");
}
template <int N>
__device__ __forceinline__ void cp_wait() {
    asm volatile("cp.async.wait_group %0;\n" :: "n"(N));
}

// ---------------------------------------------------------------------------
// tf32 rounding pass (float4)
// ---------------------------------------------------------------------------
__global__ void round_tf32_k(const float* __restrict__ src,
                             float* __restrict__ dst, int n4)
{
    int i = blockIdx.x * blockDim.x + threadIdx.x;
    if (i >= n4) return;
    float4 v = reinterpret_cast<const float4*>(src)[i];
    v.x = f2tf32f(v.x); v.y = f2tf32f(v.y);
    v.z = f2tf32f(v.z); v.w = f2tf32f(v.w);
    reinterpret_cast<float4*>(dst)[i] = v;
}

// ---------------------------------------------------------------------------
// Transpose + tf32 round: src[K][N] -> dst[N][K].  Block (32,8), 32x32 tiles.
// ---------------------------------------------------------------------------
__global__ void transpose_round_k(const float* __restrict__ src,
                                  float* __restrict__ dst, int Kdim, int Ndim)
{
    __shared__ float t[32][33];
    int n0 = blockIdx.x * 32, k0 = blockIdx.y * 32;
    int tx = threadIdx.x, ty = threadIdx.y;
    #pragma unroll
    for (int i = 0; i < 4; i++)
        t[ty + i * 8][tx] =
            f2tf32f(src[(size_t)(k0 + ty + i * 8) * Ndim + n0 + tx]);
    __syncthreads();
    #pragma unroll
    for (int i = 0; i < 4; i++)
        dst[(size_t)(n0 + ty + i * 8) * Kdim + k0 + tx] = t[tx][ty + i * 8];
}

// ---------------------------------------------------------------------------
// TF32 GEMM: ldmatrix fragments, 3-stage cp.async ring, one barrier/iter.
// A row-major [M][K], Bt row-major [N][K], pre-rounded tf32.
// BM=BN=128, BK=32, 256 thr (8 warps 2x4), warp tile 64x32.
// MODE 0: C[M,N] plain.  MODE 1: combined qkv|z epilogue with fused RoPE
//   (cols <3KDD -> g_qkv (RoPE on <2KDD), cols >=3KDD -> g_z).
// ---------------------------------------------------------------------------
#define TS_STRIDE 36
#define TILE_FLOATS (128 * TS_STRIDE)          // 4608
#define STAGE_FLOATS (2 * TILE_FLOATS)         // A + B
#define STAGE_BYTES (STAGE_FLOATS * 4)         // 36864
#define NSTAGE 3

template <int MODE>
__global__ __launch_bounds__(256, 2) void gemm_tf32(
    const float* __restrict__ A, const float* __restrict__ Bt,
    float* __restrict__ C, int M, int N, int K)
{
    extern __shared__ float sm[];
    const unsigned smem_u32 = (unsigned)__cvta_generic_to_shared(sm);

    const int tid  = threadIdx.x;
    const int wid  = tid >> 5;
    const int lane = tid & 31;
    const int r4   = lane >> 2;
    const int lc   = lane & 3;

    const int row0 = blockIdx.y * 128;
    const int col0 = blockIdx.x * 128;
    const int warp_row = (wid >> 2) * 64;
    const int warp_col = (wid & 3) * 32;

    int cp_r[4], cp_c[4];
    #pragma unroll
    for (int i = 0; i < 4; i++) {
        int idx = tid + i * 256;
        cp_r[i] = idx >> 3;  cp_c[i] = (idx & 7) * 4;
    }

    auto issue = [&](int k0, int st) {
        float* As = sm + st * STAGE_FLOATS;
        float* Bs = As + TILE_FLOATS;
        #pragma unroll
        for (int i = 0; i < 4; i++) {
            cp_async16(&As[cp_r[i] * TS_STRIDE + cp_c[i]],
                       &A[(size_t)(row0 + cp_r[i]) * K + k0 + cp_c[i]]);
            cp_async16(&Bs[cp_r[i] * TS_STRIDE + cp_c[i]],
                       &Bt[(size_t)(col0 + cp_r[i]) * K + k0 + cp_c[i]]);
        }
        cp_commit();
    };

    const int lrow = lane & 15;
    const int lcolb = (lane & 16) ? 16 : 0;
    const unsigned a_lane = smem_u32 +
        (unsigned)((warp_row + lrow) * TS_STRIDE * 4) + lcolb;
    const unsigned b_lane = smem_u32 + TILE_FLOATS * 4 +
        (unsigned)((warp_col + lrow) * TS_STRIDE * 4) + lcolb;

    float c[4][4][4];
    #pragma unroll
    for (int i = 0; i < 4; i++)
        #pragma unroll
        for (int j = 0; j < 4; j++)
            #pragma unroll
            for (int t = 0; t < 4; t++) c[i][j][t] = 0.f;

    const int nk = K >> 5;
    issue(0, 0);
    issue(32, 1);

    for (int t = 0; t < nk; t++) {
        if (t < nk - 1) cp_wait<1>(); else cp_wait<0>();
        __syncthreads();

        if (t + 2 < nk) issue((t + 2) << 5, (t + 2) % NSTAGE);

        const int cur = t % NSTAGE;
        const unsigned a_st = a_lane + cur * STAGE_BYTES;
        const unsigned b_st = b_lane + cur * STAGE_BYTES;
        #pragma unroll
        for (int kc = 0; kc < 4; kc++) {
            const unsigned koff = kc * 32;
            unsigned a[4][4], b[4][2];
            #pragma unroll
            for (int mt = 0; mt < 4; mt++)
                ldsm_x4(a[mt][0], a[mt][1], a[mt][2], a[mt][3],
                        a_st + (unsigned)(mt * 16 * TS_STRIDE * 4) + koff);
            #pragma unroll
            for (int np = 0; np < 2; np++)
                ldsm_x4(b[2*np][0], b[2*np+1][0], b[2*np][1], b[2*np+1][1],
                        b_st + (unsigned)(np * 16 * TS_STRIDE * 4) + koff);
            #pragma unroll
            for (int mt = 0; mt < 4; mt++)
                #pragma unroll
                for (int nt = 0; nt < 4; nt++)
                    mma_tf32(c[mt][nt], a[mt], b[nt]);
        }
    }

    #pragma unroll
    for (int mt = 0; mt < 4; mt++) {
        #pragma unroll
        for (int nt = 0; nt < 4; nt++) {
            int rg = row0 + warp_row + mt * 16 + r4;
            int cg = col0 + warp_col + nt * 8 + 2 * lc;
            float v0 = c[mt][nt][0], v1 = c[mt][nt][1];
            float v2 = c[mt][nt][2], v3 = c[mt][nt][3];
            if (MODE == 1) {
                if (cg < 2 * KDD) {
                    int p = (cg & (DD - 1)) >> 1;
                    int pos0 = rg & (SS - 1);
                    int pos1 = (rg + 8) & (SS - 1);
                    float c0 = g_cos[pos0 * HALF_D + p], s0 = g_sin[pos0 * HALF_D + p];
                    float c1 = g_cos[pos1 * HALF_D + p], s1 = g_sin[pos1 * HALF_D + p];
                    float o0 = v0 * c0 - v1 * s0, o1 = v0 * s0 + v1 * c0;
                    float o2 = v2 * c1 - v3 * s1, o3 = v2 * s1 + v3 * c1;
                    v0 = o0; v1 = o1; v2 = o2; v3 = o3;
                }
                if (cg < 3 * KDD) {
                    *reinterpret_cast<float2*>(
                        &g_qkv[(size_t)rg * (3 * KDD) + cg]) = make_float2(v0, v1);
                    *reinterpret_cast<float2*>(
                        &g_qkv[(size_t)(rg + 8) * (3 * KDD) + cg]) = make_float2(v2, v3);
                } else {
                    int cz = cg - 3 * KDD;
                    *reinterpret_cast<float2*>(
                        &g_z[(size_t)rg * KDD + cz]) = make_float2(v0, v1);
                    *reinterpret_cast<float2*>(
                        &g_z[(size_t)(rg + 8) * KDD + cz]) = make_float2(v2, v3);
                }
            } else {
                *reinterpret_cast<float2*>(&C[(size_t)rg * N + cg]) =
                    make_float2(v0, v1);
                *reinterpret_cast<float2*>(&C[(size_t)(rg + 8) * N + cg]) =
                    make_float2(v2, v3);
            }
        }
    }
}

// ---------------------------------------------------------------------------
// Transpose Wb|Wa (HHx8 each) into g_Wt[16][HH]
// ---------------------------------------------------------------------------
__global__ void transpose_gates_k(const float* __restrict__ Wb,
                                  const float* __restrict__ Wa)
{
    int idx = blockIdx.x * blockDim.x + threadIdx.x;
    if (idx >= 16 * HH) return;
    int n = idx / HH, k = idx % HH;
    g_Wt[idx] = (n < 8) ? Wb[(size_t)k * NHH + n]
                        : Wa[(size_t)k * NHH + (n - 8)];
}

// ---------------------------------------------------------------------------
// Gate projections: one block (512 thr) per row; warp n computes output n.
// ---------------------------------------------------------------------------
__global__ __launch_bounds__(512) void proj_gates2(const float* __restrict__ x)
{
    __shared__ float xs[HH];
    const int row = blockIdx.x;
    reinterpret_cast<float4*>(xs)[threadIdx.x] =
        reinterpret_cast<const float4*>(x + (size_t)row * HH)[threadIdx.x];
    __syncthreads();

    const int w = threadIdx.x >> 5, lane = threadIdx.x & 31;
    const float* wt = g_Wt + w * HH;
    float s = 0.f;
    #pragma unroll
    for (int it = 0; it < HH / 128; it++) {
        int k = it * 128 + lane * 4;
        float4 xv = *reinterpret_cast<const float4*>(&xs[k]);
        float4 wv = *reinterpret_cast<const float4*>(&wt[k]);
        s += xv.x * wv.x + xv.y * wv.y + xv.z * wv.z + xv.w * wv.w;
    }
    #pragma unroll
    for (int o = 16; o > 0; o >>= 1) s += __shfl_down_sync(0xffffffffu, s, o);
    if (lane == 0) {
        if (w < 8) g_bg[(size_t)row * NHH + w] = s;
        else       g_ag[(size_t)row * NHH + (w - 8)] = s;
    }
}

// ---------------------------------------------------------------------------
// RoPE tables (fp32 angle, double inv-freq)
// ---------------------------------------------------------------------------
__global__ void rope_tables_k()
{
    int idx = blockIdx.x * blockDim.x + threadIdx.x;
    if (idx >= SS * HALF_D) return;
    int pos = idx / HALF_D, i = idx % HALF_D;
    float inv = (float)exp(-((double)(2 * i) / (double)DD) * log(1.0e6));
    float ang = (float)pos * inv;
    float s, c;
    sincosf(ang, &s, &c);
    g_cos[idx] = c;
    g_sin[idx] = s;
}

// ---------------------------------------------------------------------------
// Tiled sliding-window gated attention (unchanged from R4)
// ---------------------------------------------------------------------------
#define ATS 32
__global__ __launch_bounds__(256) void attn2_k()
{
    __shared__ float ks[36 * DD];
    __shared__ float vs[36 * DD];
    __shared__ float bgs[36];
    __shared__ float ags[ATS];

    const int s_base = blockIdx.x * ATS;
    const int h = blockIdx.y, b = blockIdx.z;
    const int tid = threadIdx.x;
    const int wid = tid >> 5, lane = tid & 31;

    for (int t = tid; t < 36 * 32; t += 256) {
        int li = t >> 5, c4 = (t & 31) * 4;
        int j = s_base - 4 + li;
        float4 kv = make_float4(0.f, 0.f, 0.f, 0.f), vv = kv;
        if (j >= 0) {
            size_t r = (size_t)(b * SS + j) * (3 * KDD) + h * DD + c4;
            kv = *reinterpret_cast<const float4*>(&g_qkv[r + KDD]);
            vv = *reinterpret_cast<const float4*>(&g_qkv[r + 2 * KDD]);
        }
        *reinterpret_cast<float4*>(&ks[li * DD + c4]) = kv;
        *reinterpret_cast<float4*>(&vs[li * DD + c4]) = vv;
    }
    if (tid < 36) {
        int j = s_base - 4 + tid;
        bgs[tid] = (j >= 0) ? g_bg[(size_t)(b * SS + j) * NHH + h] : 0.f;
    }
    if (tid >= 64 && tid < 64 + ATS)
        ags[tid - 64] = g_ag[(size_t)(b * SS + s_base + tid - 64) * NHH + h];
    __syncthreads();

    const float scale = 0.08838834764831845f;

    #pragma unroll
    for (int i = 0; i < 4; i++) {
        const int sl = wid + 8 * i;
        const int s  = s_base + sl;
        const size_t orow = (size_t)(b * SS + s) * KDD + h * DD + lane * 4;

        if (s == 0) {
            *reinterpret_cast<float4*>(&g_att[orow]) =
                *reinterpret_cast<const float4*>(&vs[4 * DD + lane * 4]);
            continue;
        }

        const float4 q4 = *reinterpret_cast<const float4*>(
            &g_qkv[(size_t)(b * SS + s) * (3 * KDD) + h * DD + lane * 4]);
        const float agv = ags[sl];
        float4 acc = make_float4(0.f, 0.f, 0.f, 0.f);

        #pragma unroll
        for (int off = 0; off <= WW; off++) {
            if (s - off < 0) continue;
            const int li = sl + 4 - off;
            const float4 k4 = *reinterpret_cast<const float4*>(
                &ks[li * DD + lane * 4]);
            float part = q4.x * k4.x + q4.y * k4.y + q4.z * k4.z + q4.w * k4.w;
            #pragma unroll
            for (int o = 16; o > 0; o >>= 1)
                part += __shfl_xor_sync(0xffffffffu, part, o);
            const float gate = 1.f / (1.f + expf(-agv * bgs[li]));
            const float wgt = part * scale * gate;
            const float4 v4 = *reinterpret_cast<const float4*>(
                &vs[li * DD + lane * 4]);
            acc.x += wgt * v4.x; acc.y += wgt * v4.y;
            acc.z += wgt * v4.z; acc.w += wgt * v4.w;
        }
        *reinterpret_cast<float4*>(&g_att[orow]) = acc;
    }
}

// ---------------------------------------------------------------------------
// Gated RMS norm (emits tf32-rounded yn)
// ---------------------------------------------------------------------------
__global__ __launch_bounds__(256) void norm_k(const float* __restrict__ nw)
{
    const int row = blockIdx.x, tid = threadIdx.x;
    const size_t base = (size_t)row * KDD;

    float y[4], zz[4];
    float ss = 0.f;
    #pragma unroll
    for (int i = 0; i < 4; i++) {
        int c   = tid + i * 256;
        float zv  = g_z[base + c];
        float sig = 1.f / (1.f + expf(-zv));
        float yv  = g_att[base + c] * sig;
        y[i]  = yv;
        zz[i] = zv * sig;
        ss   += yv * yv;
    }
    __shared__ float red[8];
    #pragma unroll
    for (int o = 16; o > 0; o >>= 1) ss += __shfl_down_sync(0xffffffffu, ss, o);
    if ((tid & 31) == 0) red[tid >> 5] = ss;
    __syncthreads();
    if (tid < 8) {
        float v = red[tid];
        #pragma unroll
        for (int o = 4; o > 0; o >>= 1) v += __shfl_down_sync(0xffu, v, o);
        if (tid == 0) red[0] = v;
    }
    __syncthreads();
    const float rinv = rsqrtf(red[0] / (float)KDD + 1e-6f);

    #pragma unroll
    for (int i = 0; i < 4; i++) {
        int c = tid + i * 256;
        g_yn[base + c] = f2tf32f(y[i] * rinv * nw[c] * zz[i]);
    }
}

// ---------------------------------------------------------------------------
// Launch
// ---------------------------------------------------------------------------
extern "C" void kernel_launch(void* const* d_in, const int* in_sizes, int n_in,
                              void* d_out, int out_size)
{
    const float* x    = (const float*)d_in[0];
    const float* Wqkv = (const float*)d_in[1];
    const float* Wz   = (const float*)d_in[2];
    const float* Wb   = (const float*)d_in[3];
    const float* Wa   = (const float*)d_in[4];
    const float* nw   = (const float*)d_in[5];
    const float* Wout = (const float*)d_in[6];
    float* out = (float*)d_out;

    float *p_xr, *p_Wcomb, *p_Woutr, *p_yn;
    cudaGetSymbolAddress((void**)&p_xr,    g_xr);
    cudaGetSymbolAddress((void**)&p_Wcomb, g_Wcomb);
    cudaGetSymbolAddress((void**)&p_Woutr, g_Woutr);
    cudaGetSymbolAddress((void**)&p_yn,    g_yn);

    const int smem_bytes = NSTAGE * STAGE_BYTES;   // 110592
    static bool attr_set = false;
    if (!attr_set) {
        cudaFuncSetAttribute(gemm_tf32<0>,
            cudaFuncAttributeMaxDynamicSharedMemorySize, smem_bytes);
        cudaFuncSetAttribute(gemm_tf32<1>,
            cudaFuncAttributeMaxDynamicSharedMemorySize, smem_bytes);
        attr_set = true;
    }

    // 1) Round x; transpose+round weights; rope tables; gate transpose
    {
        int n = MM * HH / 4;
        round_tf32_k<<<(n + 255) / 256, 256>>>(x, p_xr, n);
        dim3 blk(32, 8);
        transpose_round_k<<<dim3(3 * KDD / 32, HH / 32), blk>>>(
            Wqkv, p_Wcomb, HH, 3 * KDD);
        transpose_round_k<<<dim3(KDD / 32, HH / 32), blk>>>(
            Wz, p_Wcomb + (size_t)3 * KDD * HH, HH, KDD);
        transpose_round_k<<<dim3(HH / 32, KDD / 32), blk>>>(
            Wout, p_Woutr, KDD, HH);
        int t = SS * HALF_D;
        rope_tables_k<<<(t + 255) / 256, 256>>>();
        int m = 16 * HH;
        transpose_gates_k<<<(m + 255) / 256, 256>>>(Wb, Wa);
    }

    // 2) Combined qkv|z projection (RoPE fused)
    {
        dim3 g(NCOMB / 128, MM / 128);
        gemm_tf32<1><<<g, 256, smem_bytes>>>(p_xr, p_Wcomb, nullptr,
                                             MM, NCOMB, HH);
    }

    // 3) Gate projections
    proj_gates2<<<MM, 512>>>(x);

    // 4) Tiled sliding-window gated attention
    {
        dim3 g(SS / ATS, NHH, BB);
        attn2_k<<<g, 256>>>();
    }

    // 5) Gated RMS norm
    norm_k<<<MM, 256>>>(nw);

    // 6) Output projection
    {
        dim3 g(HH / 128, MM / 128);
        gemm_tf32<0><<<g, 256, smem_bytes>>>(p_yn, p_Woutr, out, MM, HH, KDD);
    }
}